// round 17
// baseline (speedup 1.0000x reference)
#include <cuda_runtime.h>
#include <cuda_fp16.h>
#include <math.h>
#include <stdint.h>

#define BATCH 2
#define NSEQ 4096
#define DIM 512
#define HEADS 8
#define DH 64
#define ROWS (BATCH * NSEQ)
#define QKV_COLS (3 * DIM)
#define QS 0.18033688011112042f   // 0.125 * log2(e); p = 2^(s*QS) directly

typedef unsigned int u32;
typedef unsigned short u16;

// ---- fp16 buffers (device globals; no runtime alloc) ----
__device__ u16 g_xhi[ROWS * DIM];
__device__ u16 g_wqT[QKV_COLS * DIM];
__device__ u16 g_woT[DIM * DIM];
__device__ u16 g_qhi[ROWS * QKV_COLS];
__device__ u16 g_ahi[ROWS * DIM];

// ---------------- helpers ----------------
__device__ __forceinline__ u32 smem_u32(const void* p) {
    u32 a; asm("{ .reg .u64 t; cvta.to.shared.u64 t, %1; cvt.u32.u64 %0, t; }"
               : "=r"(a) : "l"(p)); return a;
}
__device__ __forceinline__ float ex2f(float x) {
    float r; asm("ex2.approx.f32 %0, %1;" : "=f"(r) : "f"(x)); return r;
}
__device__ __forceinline__ u32 packh2(float a, float b) {
    u32 h; asm("cvt.rn.f16x2.f32 %0, %1, %2;" : "=r"(h) : "f"(b), "f"(a)); return h;
}
__device__ __forceinline__ void mma16816(float* d, const u32* a, u32 b0, u32 b1) {
    asm volatile("mma.sync.aligned.m16n8k16.row.col.f32.f16.f16.f32 "
        "{%0,%1,%2,%3}, {%4,%5,%6,%7}, {%8,%9}, {%0,%1,%2,%3};"
        : "+f"(d[0]), "+f"(d[1]), "+f"(d[2]), "+f"(d[3])
        : "r"(a[0]), "r"(a[1]), "r"(a[2]), "r"(a[3]), "r"(b0), "r"(b1));
}
__device__ __forceinline__ void ldsm4(u32 a, u32& r0, u32& r1, u32& r2, u32& r3) {
    asm volatile("ldmatrix.sync.aligned.m8n8.x4.shared.b16 {%0,%1,%2,%3}, [%4];"
        : "=r"(r0), "=r"(r1), "=r"(r2), "=r"(r3) : "r"(a));
}
__device__ __forceinline__ void ldsm4t(u32 a, u32& r0, u32& r1, u32& r2, u32& r3) {
    asm volatile("ldmatrix.sync.aligned.m8n8.x4.trans.shared.b16 {%0,%1,%2,%3}, [%4];"
        : "=r"(r0), "=r"(r1), "=r"(r2), "=r"(r3) : "r"(a));
}
#define CPA16(d, s) asm volatile("cp.async.cg.shared.global [%0], [%1], 16;" :: "r"(d), "l"(s) : "memory")
#define CPA_COMMIT() asm volatile("cp.async.commit_group;" ::: "memory")
#define CPA_WAIT0()  asm volatile("cp.async.wait_group 0;" ::: "memory")
#define CPA_WAIT1()  asm volatile("cp.async.wait_group 1;" ::: "memory")
#define CPA_WAIT2()  asm volatile("cp.async.wait_group 2;" ::: "memory")

// ------- merged prepass: x -> fp16 | w_qkv^T -> fp16 | w_out^T -> fp16 ------
__global__ void prepass(const float* __restrict__ x,  u16* __restrict__ xhi,
                        const float* __restrict__ wq, u16* __restrict__ wqT,
                        const float* __restrict__ wo, u16* __restrict__ woT)
{
    __shared__ float tile[32][33];
    const int bid = blockIdx.x, tid = threadIdx.x;
    if (bid < 4096) {
        const int i = bid * 256 + tid;
        const float4 v = ((const float4*)x)[i];
        ((u32*)xhi)[2 * i]     = packh2(v.x, v.y);
        ((u32*)xhi)[2 * i + 1] = packh2(v.z, v.w);
        return;
    }
    const float* w; u16* oT; int N, bb;
    if (bid < 4864) { w = wq; oT = wqT; N = 1536; bb = bid - 4096; }
    else            { w = wo; oT = woT; N = 512;  bb = bid - 4864; }
    const int nb = N / 32;
    const int n0 = (bb % nb) * 32, k0 = (bb / nb) * 32;
    const int tx = tid & 31, ty = tid >> 5;   // 32 x 8
#pragma unroll
    for (int i = 0; i < 4; i++)
        tile[ty + i * 8][tx] = w[(size_t)(k0 + ty + i * 8) * N + n0 + tx];
    __syncthreads();
#pragma unroll
    for (int i = 0; i < 4; i++) {
        u16 h;
        asm("cvt.rn.f16.f32 %0, %1;" : "=h"(h) : "f"(tile[tx][ty + i * 8]));
        oT[(size_t)(n0 + ty + i * 8) * 512 + k0 + tx] = h;
    }
}

// ---- fp16 GEMM: C = Ah @ Bh. 4 warps, 64x64 warp tile, BK=64, 3-stage -----
// dyn smem: [3 stages][Ah 18432B | Bh 18432B] = 110592B (144B row stride)
// pipeline: prefetch distance 2 == stages-1 (issue s+2, wait_group 1)
template <int MODE>
__global__ __launch_bounds__(128, 2) void gemm_fp16(
    const u16* __restrict__ Ahi, const u16* __restrict__ BThi,
    u16* __restrict__ Chi,
    float* __restrict__ Cf, const float* __restrict__ bias)
{
    extern __shared__ __align__(16) u16 dyng[];
    const u32 smb = smem_u32(dyng);
    const int tid = threadIdx.x, w = tid >> 5, l = tid & 31;
    const int g = l >> 2, c = l & 3;
    const int wm = w & 1, wn = w >> 1;               // 2 x 2 warp grid
    const int row0 = blockIdx.y * 128, col0 = blockIdx.x * 128;
    const u32 jj = (u32)(l >> 3);
    const u32 aoff = (u32)((wm * 64 + (jj & 1) * 8 + (l & 7)) * 144 + (jj >> 1) * 16);
    const u32 boff = (u32)(18432 + (wn * 64 + (jj >> 1) * 8 + (l & 7)) * 144 + (jj & 1) * 16);

    auto issue = [&](int k0, int st) {
        const u32 base = smb + st * 36864;
#pragma unroll
        for (int i = 0; i < 8; i++) {
            const int idx = i * 128 + tid, r = idx >> 3, ff = (idx & 7) * 8;
            const u32 d = base + (u32)(r * 144 + ff * 2);
            CPA16(d,         Ahi + (size_t)(row0 + r) * 512 + k0 + ff);
            CPA16(d + 18432, BThi + (size_t)(col0 + r) * 512 + k0 + ff);
        }
    };

    float acc[4][8][4];
#pragma unroll
    for (int mt = 0; mt < 4; mt++)
#pragma unroll
        for (int nt = 0; nt < 8; nt++)
#pragma unroll
            for (int i = 0; i < 4; i++) acc[mt][nt][i] = 0.0f;

    issue(0, 0);  CPA_COMMIT();
    issue(64, 1); CPA_COMMIT();
    for (int s = 0; s < 8; s++) {
        if (s < 7) { CPA_WAIT1(); } else { CPA_WAIT0(); }
        __syncthreads();
        if (s + 2 < 8) { issue((s + 2) * 64, (s + 2) % 3); CPA_COMMIT(); }
        const u32 ab = smb + (s % 3) * 36864 + aoff;
        const u32 bb = smb + (s % 3) * 36864 + boff;
#pragma unroll
        for (int ks = 0; ks < 4; ks++) {
            u32 ah[4][4], bh[8][2];
#pragma unroll
            for (int mt = 0; mt < 4; mt++)
                ldsm4(ab + mt * 2304 + ks * 32, ah[mt][0], ah[mt][1], ah[mt][2], ah[mt][3]);
#pragma unroll
            for (int ntp = 0; ntp < 4; ntp++)
                ldsm4(bb + ntp * 2304 + ks * 32,
                      bh[2 * ntp][0], bh[2 * ntp][1], bh[2 * ntp + 1][0], bh[2 * ntp + 1][1]);
#pragma unroll
            for (int mt = 0; mt < 4; mt++)
#pragma unroll
                for (int nt = 0; nt < 8; nt++)
                    mma16816(acc[mt][nt], ah[mt], bh[nt][0], bh[nt][1]);
        }
    }

#pragma unroll
    for (int mt = 0; mt < 4; mt++) {
        const int r0g = row0 + wm * 64 + mt * 16 + g;
#pragma unroll
        for (int nt = 0; nt < 8; nt++) {
            const int cc = col0 + wn * 64 + nt * 8 + 2 * c;
            if (MODE == 0) {
                const float sc = (cc >= 512 && cc < 1024) ? QS : 1.0f;
                *(u32*)&Chi[(size_t)r0g * 1536 + cc] =
                    packh2(acc[mt][nt][0] * sc, acc[mt][nt][1] * sc);
                *(u32*)&Chi[(size_t)(r0g + 8) * 1536 + cc] =
                    packh2(acc[mt][nt][2] * sc, acc[mt][nt][3] * sc);
            } else {
                const float b0 = bias[cc], b1 = bias[cc + 1];
                *(float2*)&Cf[(size_t)r0g * 512 + cc] =
                    make_float2(acc[mt][nt][0] + b0, acc[mt][nt][1] + b1);
                *(float2*)&Cf[(size_t)(r0g + 8) * 512 + cc] =
                    make_float2(acc[mt][nt][2] + b0, acc[mt][nt][3] + b1);
            }
        }
    }
}

// ---- flash attention: fp16, cross-tile S pipeline, scalar lsum ------------
// S = Qh·Kh;  p = 2^S;  O += Ph·Vh;  lsum on FMA pipe (tensor pipe is binding).
// dyn smem: [4 stages][Kh 9216B | Vh 9216B] = 73728B
__global__ __launch_bounds__(128, 2) void attn_kernel(
    const u16* __restrict__ qhi, u16* __restrict__ ohi)
{
    extern __shared__ __align__(16) u16 dynsm[];
    const int t = threadIdx.x, w = t >> 5, l = t & 31;
    const int g = l >> 2, c = l & 3;
    const int qb = blockIdx.x, h = blockIdx.y, b = blockIdx.z;
    const int rowbase = qb * 128 + w * 32;
    const u32 smb = smem_u32(dynsm);
    const u32 jj = (u32)(l >> 3);
    const u32 koff = (u32)((((l >> 4) & 1) * 8 + (l & 7)) * 144 + ((l >> 3) & 1) * 16);
    const u32 voff = (u32)(9216 + ((jj & 1) * 8 + (l & 7)) * 144 + (jj >> 1) * 16);

    const size_t kvrow0 = (size_t)(b * NSEQ) * 1536;
    auto issue_tile = [&](int kt, int st) {
        const size_t rb = kvrow0 + (size_t)kt * 64 * 1536;
        const u16* kh = qhi + rb + 512 + h * DH;
        const u16* vh = qhi + rb + 1024 + h * DH;
        const u32 base = smb + st * 18432;
#pragma unroll
        for (int i = 0; i < 4; i++) {
            const int idx = i * 128 + t, key = idx >> 3, f = (idx & 7) * 8;
            const u32 d = base + (u32)(key * 144 + f * 2);
            const size_t so = (size_t)key * 1536 + f;
            CPA16(d,        kh + so);
            CPA16(d + 9216, vh + so);
        }
    };

    issue_tile(0, 0); CPA_COMMIT();
    issue_tile(1, 1); CPA_COMMIT();
    issue_tile(2, 2); CPA_COMMIT();

    u32 qh[2][4][4];
    {
        const u16* ph = qhi + (size_t)(b * NSEQ + rowbase) * 1536 + h * DH;
#pragma unroll
        for (int mt = 0; mt < 2; mt++)
#pragma unroll
            for (int ks = 0; ks < 4; ks++) {
                const size_t i0 = (size_t)(mt * 16 + g) * 1536 + ks * 16 + c * 2;
                qh[mt][ks][0] = *(const u32*)&ph[i0];
                qh[mt][ks][1] = *(const u32*)&ph[i0 + 8 * 1536];
                qh[mt][ks][2] = *(const u32*)&ph[i0 + 8];
                qh[mt][ks][3] = *(const u32*)&ph[i0 + 8 * 1536 + 8];
            }
    }

    float o[2][8][4];
#pragma unroll
    for (int mt = 0; mt < 2; mt++)
#pragma unroll
        for (int nt = 0; nt < 8; nt++)
#pragma unroll
            for (int i = 0; i < 4; i++) o[mt][nt][i] = 0.0f;
    float lsum[2][2] = { {0.0f, 0.0f}, {0.0f, 0.0f} };

    // prologue: S(tile 0, ch 0)
    float scur[2][8];
    {
        CPA_WAIT2();
        __syncthreads();
        u32 kh4[4][4];
#pragma unroll
        for (int ks = 0; ks < 4; ks++)
            ldsm4(smb + koff + ks * 32, kh4[ks][0], kh4[ks][1], kh4[ks][2], kh4[ks][3]);
#pragma unroll
        for (int mt = 0; mt < 2; mt++) {
#pragma unroll
            for (int i = 0; i < 8; i++) scur[mt][i] = 0.0f;
#pragma unroll
            for (int ks = 0; ks < 4; ks++) {
                mma16816(scur[mt],     qh[mt][ks], kh4[ks][0], kh4[ks][1]);
                mma16816(scur[mt] + 4, qh[mt][ks], kh4[ks][2], kh4[ks][3]);
            }
        }
    }

    for (int kt = 0; kt < NSEQ / 64; kt++) {
        if (kt <= 61) { CPA_WAIT1(); } else { CPA_WAIT0(); }
        __syncthreads();
        if (kt + 3 < NSEQ / 64) { issue_tile(kt + 3, (kt + 3) & 3); CPA_COMMIT(); }
        const u32 kb0 = smb + (kt & 3) * 18432 + koff;
        const u32 vb0 = smb + (kt & 3) * 18432 + voff;
        const u32 kb1 = smb + ((kt + 1) & 3) * 18432 + koff;

#pragma unroll
        for (int ch = 0; ch < 4; ch++) {
            u32 vbh[8][2];
#pragma unroll
            for (int ntp = 0; ntp < 4; ntp++) {
                const u32 a0 = vb0 + ch * 2304 + ntp * 32;
                ldsm4t(a0, vbh[2 * ntp][0], vbh[2 * ntp][1], vbh[2 * ntp + 1][0], vbh[2 * ntp + 1][1]);
            }
            float snext[2][8];
            const bool have_next = (ch < 3) || (kt + 1 < NSEQ / 64);
            if (have_next) {
                const u32 kbase = (ch < 3) ? (kb0 + (ch + 1) * 2304) : kb1;
                u32 kh4[4][4];
#pragma unroll
                for (int ks = 0; ks < 4; ks++)
                    ldsm4(kbase + ks * 32, kh4[ks][0], kh4[ks][1], kh4[ks][2], kh4[ks][3]);
#pragma unroll
                for (int mt = 0; mt < 2; mt++) {
#pragma unroll
                    for (int i = 0; i < 8; i++) snext[mt][i] = 0.0f;
#pragma unroll
                    for (int ks = 0; ks < 4; ks++) {
                        mma16816(snext[mt],     qh[mt][ks], kh4[ks][0], kh4[ks][1]);
                        mma16816(snext[mt] + 4, qh[mt][ks], kh4[ks][2], kh4[ks][3]);
                    }
                }
            }
            // exp + pack + scalar lsum (MUFU/FMA pipes — overlap snext tensor work)
            u32 pa[2][4];
#pragma unroll
            for (int mt = 0; mt < 2; mt++) {
                float p[8];
#pragma unroll
                for (int i = 0; i < 8; i++) p[i] = ex2f(scur[mt][i]);
                lsum[mt][0] += p[0] + p[1] + p[4] + p[5];
                lsum[mt][1] += p[2] + p[3] + p[6] + p[7];
                pa[mt][0] = packh2(p[0], p[1]);
                pa[mt][1] = packh2(p[2], p[3]);
                pa[mt][2] = packh2(p[4], p[5]);
                pa[mt][3] = packh2(p[6], p[7]);
            }
#pragma unroll
            for (int mt = 0; mt < 2; mt++)
#pragma unroll
                for (int nt = 0; nt < 8; nt++)
                    mma16816(o[mt][nt], pa[mt], vbh[nt][0], vbh[nt][1]);
            if (have_next) {
#pragma unroll
                for (int mt = 0; mt < 2; mt++)
#pragma unroll
                    for (int i = 0; i < 8; i++) scur[mt][i] = snext[mt][i];
            }
        }
    }

    // epilogue: reduce lsum across the 4 lanes of each row group
#pragma unroll
    for (int mt = 0; mt < 2; mt++)
#pragma unroll
        for (int rh = 0; rh < 2; rh++) {
            lsum[mt][rh] += __shfl_xor_sync(0xffffffffu, lsum[mt][rh], 1);
            lsum[mt][rh] += __shfl_xor_sync(0xffffffffu, lsum[mt][rh], 2);
        }
#pragma unroll
    for (int mt = 0; mt < 2; mt++) {
        const float inv0 = 1.0f / lsum[mt][0], inv1 = 1.0f / lsum[mt][1];
        const size_t r0 = (size_t)(b * NSEQ + rowbase + mt * 16 + g);
        const size_t base0 = r0 * 512 + h * DH + c * 2;
        const size_t base1 = base0 + 8 * 512;
#pragma unroll
        for (int nt = 0; nt < 8; nt++) {
            *(u32*)&ohi[base0 + nt * 8] = packh2(o[mt][nt][0] * inv0, o[mt][nt][1] * inv0);
            *(u32*)&ohi[base1 + nt * 8] = packh2(o[mt][nt][2] * inv1, o[mt][nt][3] * inv1);
        }
    }
}

// ---------------- launch ----------------
extern "C" void kernel_launch(void* const* d_in, const int* in_sizes, int n_in,
                              void* d_out, int out_size)
{
    const float* x     = (const float*)d_in[0];
    const float* w_qkv = (const float*)d_in[1];
    const float* w_out = (const float*)d_in[2];
    const float* b_out = (const float*)d_in[3];
    float* out = (float*)d_out;

    u16 *xhi, *wqh, *woh, *qhi, *ahi;
    void* p;
    cudaGetSymbolAddress(&p, g_xhi); xhi = (u16*)p;
    cudaGetSymbolAddress(&p, g_wqT); wqh = (u16*)p;
    cudaGetSymbolAddress(&p, g_woT); woh = (u16*)p;
    cudaGetSymbolAddress(&p, g_qhi); qhi = (u16*)p;
    cudaGetSymbolAddress(&p, g_ahi); ahi = (u16*)p;

    cudaFuncSetAttribute(gemm_fp16<0>, cudaFuncAttributeMaxDynamicSharedMemorySize, 110592);
    cudaFuncSetAttribute(gemm_fp16<1>, cudaFuncAttributeMaxDynamicSharedMemorySize, 110592);
    cudaFuncSetAttribute(attn_kernel,  cudaFuncAttributeMaxDynamicSharedMemorySize, 73728);

    prepass<<<5120, 256>>>(x, xhi, w_qkv, wqh, w_out, woh);

    { dim3 g(QKV_COLS / 128, ROWS / 128);
      gemm_fp16<0><<<g, 128, 110592>>>(xhi, wqh, qhi, nullptr, nullptr); }
    { dim3 g(NSEQ / 128, HEADS, BATCH);
      attn_kernel<<<g, 128, 73728>>>(qhi, ahi); }
    { dim3 g(DIM / 128, ROWS / 128);
      gemm_fp16<1><<<g, 128, 110592>>>(ahi, woh, nullptr, out, b_out); }
}